// round 9
// baseline (speedup 1.0000x reference)
#include <cuda_runtime.h>

// Problem constants
#define HH   64
#define WW   64
#define CIN  48
#define OCC  192   // 4*F gate channels
#define BB   4
#define TT   16
#define NF   48

// Tile: 8 wide x 4 tall spatial, all 192 oc per block.
// Dynamic smem: patch 6*10*48 (2880) + weights 48*192 (9216) = 12096 floats.
// z-phase reuses the region (needs 32*192 = 6144 floats).
#define PATCH_FLOATS 2880
#define SMEM_FLOATS  (PATCH_FLOATS + 9216)
#define SMEM_BYTES   (SMEM_FLOATS * 4)

typedef unsigned long long u64;

// Scratch (device globals -- no runtime allocation allowed)
__device__ float g_zx[(size_t)BB * TT * HH * WW * OCC];  // precomputed conv(x,Wx)+b per layer
__device__ float g_h1[(size_t)BB * TT * HH * WW * NF];   // layer-1 output sequence
__device__ float g_hA[(size_t)BB * HH * WW * NF];        // recurrent h (double-buffered)
__device__ float g_hB[(size_t)BB * HH * WW * NF];
__device__ float g_c [(size_t)BB * HH * WW * NF];        // cell state

__global__ void zero_state_kernel() {
    size_t n = (size_t)BB * HH * WW * NF;
    for (size_t i = (size_t)blockIdx.x * blockDim.x + threadIdx.x; i < n;
         i += (size_t)gridDim.x * blockDim.x) {
        g_hA[i] = 0.f;
        g_c[i]  = 0.f;
    }
}

__device__ __forceinline__ float hsig(float x) {
    return __saturatef(x * (1.0f / 6.0f) + 0.5f);
}

// ---- packed f32x2 helpers (Blackwell FFMA2) ----
__device__ __forceinline__ u64 bcast2(float x) {
    u64 r;
    asm("mov.b64 %0, {%1, %1};" : "=l"(r) : "f"(x));
    return r;
}
__device__ __forceinline__ void ffma2(u64& d, u64 a, u64 b) {
    asm("fma.rn.f32x2 %0, %1, %2, %0;" : "+l"(d) : "l"(a), "l"(b));
}

// Load 6x10x48 input patch (zero-padded) into smem, optionally applying BN.
// BN applies ONLY to in-bounds pixels -- padding of the normalized tensor is exact zero.
template <bool BN>
__device__ __forceinline__ void load_patch(const float* __restrict__ src,  // image base [H,W,48]
                                           float* s_in, int gy0, int gx0, int tid,
                                           const float* s_scale, const float* s_shift) {
    for (int p = tid; p < PATCH_FLOATS / 4; p += 256) {  // 60 pixels * 12 float4
        int pix = p / 12, cv = p - pix * 12;
        int py = pix / 10, px = pix - py * 10;
        int gy = gy0 + py, gx = gx0 + px;
        float4 v = make_float4(0.f, 0.f, 0.f, 0.f);
        if ((unsigned)gy < HH && (unsigned)gx < WW) {
            v = *(const float4*)(src + ((size_t)gy * WW + gx) * CIN + cv * 4);
            if (BN) {
                int c = cv * 4;
                v.x = v.x * s_scale[c + 0] + s_shift[c + 0];
                v.y = v.y * s_scale[c + 1] + s_shift[c + 1];
                v.z = v.z * s_scale[c + 2] + s_shift[c + 2];
                v.w = v.w * s_scale[c + 3] + s_shift[c + 3];
            }
        }
        ((float4*)s_in)[p] = v;
    }
}

// Conv core: accumulate 3x3x48 -> 192 for this thread's 2 spatial x 6 packed-oc-pair tile.
// Thread og (0..15) owns oc pairs {32*j + 2*og : j=0..5} -> weight LDS.64 conflict-free.
__device__ __forceinline__ void conv_accum(const float* __restrict__ Wg,  // [3,3,48,192]
                                           const float* s_in, float* s_w,
                                           u64 acc[2][6],
                                           int tid, int sy, int sx0, int og) {
#pragma unroll 1
    for (int kk = 0; kk < 9; kk++) {
        __syncthreads();
        // stage 48x192 weight slice for this (kh,kw)
        const float4* wsrc = (const float4*)(Wg + (size_t)kk * CIN * OCC);
        float4* wdst = (float4*)s_w;
#pragma unroll
        for (int p = 0; p < 9; p++) wdst[tid + p * 256] = wsrc[tid + p * 256];
        __syncthreads();

        int kh = kk / 3, kw = kk - kh * 3;
        const float* inrow = s_in + ((sy + kh) * 10 + sx0 + kw) * CIN;
        const float* wcol = s_w + 2 * og;
#pragma unroll 2
        for (int c = 0; c < CIN; c++) {
            u64 a0 = bcast2(inrow[c]);
            u64 a1 = bcast2(inrow[c + CIN]);
            const u64* w2 = (const u64*)(wcol + c * OCC);
            u64 wv[6];
#pragma unroll
            for (int j = 0; j < 6; j++) wv[j] = w2[16 * j];  // stride 32 floats
#pragma unroll
            for (int j = 0; j < 6; j++) {
                ffma2(acc[0][j], a0, wv[j]);
                ffma2(acc[1][j], a1, wv[j]);
            }
        }
    }
}

// conv(input, Wx) + b over all 64 (b,t) images. BN=true reads g_h1 and applies BN first.
template <bool BN>
__global__ void __launch_bounds__(256, 4) convx_kernel(
    const float* __restrict__ xin, const float* __restrict__ Wx,
    const float* __restrict__ bias,
    const float* __restrict__ gamma, const float* __restrict__ beta,
    const float* __restrict__ mean, const float* __restrict__ var) {
    extern __shared__ float sm[];
    float* s_in = sm;                 // 2880 floats
    float* s_w  = sm + PATCH_FLOATS;  // 9216 floats
    __shared__ float s_scale[CIN], s_shift[CIN];

    int tid = threadIdx.x;
    int img = blockIdx.z;  // b*T + t
    int gy0 = blockIdx.y * 4 - 1, gx0 = blockIdx.x * 8 - 1;

    if (BN) {
        if (tid < CIN) {
            float sc = gamma[tid] * rsqrtf(var[tid] + 1e-3f);
            s_scale[tid] = sc;
            s_shift[tid] = beta[tid] - mean[tid] * sc;
        }
        __syncthreads();
    }
    const float* src = BN ? (g_h1 + (size_t)img * HH * WW * NF)
                          : (xin + (size_t)img * HH * WW * CIN);
    load_patch<BN>(src, s_in, gy0, gx0, tid, s_scale, s_shift);

    int og = tid & 15, sg = tid >> 4;      // sg 0..15: 16 spatial pairs
    int sy = sg >> 2, sx0 = (sg & 3) * 2;  // sy 0..3, sx0 in {0,2,4,6}

    u64 acc[2][6];
    {
        const float* bp = bias + 2 * og;
#pragma unroll
        for (int j = 0; j < 6; j++) {
            u64 bv = *(const u64*)(bp + 32 * j);
            acc[0][j] = bv; acc[1][j] = bv;
        }
    }
    conv_accum(Wx, s_in, s_w, acc, tid, sy, sx0, og);

#pragma unroll
    for (int i = 0; i < 2; i++) {
        int y = blockIdx.y * 4 + sy, x = blockIdx.x * 8 + sx0 + i;
        float* dst = g_zx + (((size_t)img * HH + y) * WW + x) * OCC + 2 * og;
#pragma unroll
        for (int j = 0; j < 6; j++)
            *(u64*)(dst + 32 * j) = acc[i][j];
    }
}

// One recurrent step: z = zx[t] + conv(h,Wh); gates; update c,h.
// LAYER 1 -> write h to g_h1 sequence; LAYER 2 -> write out = x + h.
template <int LAYER>
__global__ void __launch_bounds__(256, 4) step_kernel(
    const float* __restrict__ Wh, int t, int parity,
    const float* __restrict__ xres, float* __restrict__ out) {
    extern __shared__ float sm[];
    float* s_in = sm;
    float* s_w  = sm + PATCH_FLOATS;
    float* s_z  = sm;  // reuses patch+weight region after conv (needs 6144 floats)

    int tid = threadIdx.x;
    int b = blockIdx.z;
    int gy0 = blockIdx.y * 4 - 1, gx0 = blockIdx.x * 8 - 1;

    const float* hin = parity ? g_hB : g_hA;
    float* hout      = parity ? g_hA : g_hB;

    load_patch<false>(hin + (size_t)b * HH * WW * NF, s_in, gy0, gx0, tid, nullptr, nullptr);

    int og = tid & 15, sg = tid >> 4;
    int sy = sg >> 2, sx0 = (sg & 3) * 2;

    u64 acc[2][6];
#pragma unroll
    for (int i = 0; i < 2; i++)
#pragma unroll
        for (int j = 0; j < 6; j++) acc[i][j] = 0ull;

    conv_accum(Wh, s_in, s_w, acc, tid, sy, sx0, og);

    __syncthreads();  // all smem reads done; safe to overwrite with z
#pragma unroll
    for (int i = 0; i < 2; i++) {
        int s = sy * 8 + sx0 + i;  // 0..31 local spatial
        float* dst = s_z + s * OCC + 2 * og;
#pragma unroll
        for (int j = 0; j < 6; j++)
            *(u64*)(dst + 32 * j) = acc[i][j];  // banks 2og,2og+1: conflict-free
    }
    __syncthreads();

    int imgt = b * TT + t;
#pragma unroll 1
    for (int k = 0; k < 6; k++) {
        int e = tid + k * 256;         // 0..1535: 32 spatial x 48 f-channels
        int s = e / 48, f = e - s * 48;
        int yy = gy0 + 1 + (s >> 3);
        int xx = gx0 + 1 + (s & 7);
        size_t zoff = (((size_t)imgt * HH + yy) * WW + xx) * OCC;
        const float* zx = g_zx + zoff;
        float zi = s_z[s * OCC + f]          + zx[f];
        float zf = s_z[s * OCC + f + NF]     + zx[f + NF];
        float zg = s_z[s * OCC + f + 2 * NF] + zx[f + 2 * NF];
        float zo = s_z[s * OCC + f + 3 * NF] + zx[f + 3 * NF];

        size_t hoff = (((size_t)b * HH + yy) * WW + xx) * NF + f;
        float cold = g_c[hoff];
        float cn = hsig(zf) * cold + hsig(zi) * tanhf(zg);
        float hn = hsig(zo) * tanhf(cn);
        g_c[hoff]  = cn;
        hout[hoff] = hn;

        size_t ooff = (((size_t)imgt * HH + yy) * WW + xx) * NF + f;
        if (LAYER == 1)
            g_h1[ooff] = hn;
        else
            out[ooff] = xres[ooff] + hn;
    }
}

extern "C" void kernel_launch(void* const* d_in, const int* in_sizes, int n_in,
                              void* d_out, int out_size) {
    const float* x     = (const float*)d_in[0];
    const float* Wx1   = (const float*)d_in[1];
    const float* Wh1   = (const float*)d_in[2];
    const float* b1    = (const float*)d_in[3];
    const float* Wx2   = (const float*)d_in[4];
    const float* Wh2   = (const float*)d_in[5];
    const float* b2    = (const float*)d_in[6];
    const float* gamma = (const float*)d_in[7];
    const float* beta  = (const float*)d_in[8];
    const float* mean  = (const float*)d_in[9];
    const float* var   = (const float*)d_in[10];
    float* out = (float*)d_out;

    cudaFuncSetAttribute((const void*)convx_kernel<false>,
                         cudaFuncAttributeMaxDynamicSharedMemorySize, SMEM_BYTES);
    cudaFuncSetAttribute((const void*)convx_kernel<true>,
                         cudaFuncAttributeMaxDynamicSharedMemorySize, SMEM_BYTES);
    cudaFuncSetAttribute((const void*)step_kernel<1>,
                         cudaFuncAttributeMaxDynamicSharedMemorySize, SMEM_BYTES);
    cudaFuncSetAttribute((const void*)step_kernel<2>,
                         cudaFuncAttributeMaxDynamicSharedMemorySize, SMEM_BYTES);

    dim3 blk(256);
    dim3 gridx(8, 16, BB * TT);  // 8x4 tiles over all (b,t) images
    dim3 grids(8, 16, BB);       // one recurrent step

    // ---- Layer 1 ----
    zero_state_kernel<<<256, 256>>>();
    convx_kernel<false><<<gridx, blk, SMEM_BYTES>>>(x, Wx1, b1,
                                                    nullptr, nullptr, nullptr, nullptr);
    for (int t = 0; t < TT; t++)
        step_kernel<1><<<grids, blk, SMEM_BYTES>>>(Wh1, t, t & 1, nullptr, nullptr);

    // ---- Layer 2 (BN folded into Zx conv's input load) ----
    zero_state_kernel<<<256, 256>>>();
    convx_kernel<true><<<gridx, blk, SMEM_BYTES>>>(nullptr, Wx2, b2,
                                                   gamma, beta, mean, var);
    for (int t = 0; t < TT; t++)
        step_kernel<2><<<grids, blk, SMEM_BYTES>>>(Wh2, t, t & 1, x, out);
}

// round 10
// speedup vs baseline: 1.4127x; 1.4127x over previous
#include <cuda_runtime.h>

// Problem constants
#define HH   64
#define WW   64
#define CIN  48
#define OCC  192   // 4*F gate channels
#define BB   4
#define TT   16
#define NF   48

// Tile: 8 wide x 4 tall spatial (32 px), all 192 oc per block, 128 threads.
// Per thread: 4 spatial x 12 oc (6 packed pairs)  -> same smem-traffic/FMA as R8.
// Dynamic smem: patch 6*10*48 (2880) + weights 48*192 (9216) = 12096 floats (48.4 KB).
// z-phase reuses the region (needs 32*192 = 6144 floats).
#define PATCH_FLOATS 2880
#define SMEM_FLOATS  (PATCH_FLOATS + 9216)
#define SMEM_BYTES   (SMEM_FLOATS * 4)

typedef unsigned long long u64;

// Scratch (device globals -- no runtime allocation allowed)
__device__ float g_zx[(size_t)BB * TT * HH * WW * OCC];  // precomputed conv(x,Wx)+b per layer
__device__ float g_h1[(size_t)BB * TT * HH * WW * NF];   // layer-1 output sequence
__device__ float g_hA[(size_t)BB * HH * WW * NF];        // recurrent h (double-buffered)
__device__ float g_hB[(size_t)BB * HH * WW * NF];
__device__ float g_c [(size_t)BB * HH * WW * NF];        // cell state

__global__ void zero_state_kernel() {
    size_t n = (size_t)BB * HH * WW * NF;
    for (size_t i = (size_t)blockIdx.x * blockDim.x + threadIdx.x; i < n;
         i += (size_t)gridDim.x * blockDim.x) {
        g_hA[i] = 0.f;
        g_c[i]  = 0.f;
    }
}

__device__ __forceinline__ float hsig(float x) {
    return __saturatef(x * (1.0f / 6.0f) + 0.5f);
}

// ---- packed f32x2 helpers (Blackwell FFMA2) ----
__device__ __forceinline__ u64 bcast2(float x) {
    u64 r;
    asm("mov.b64 %0, {%1, %1};" : "=l"(r) : "f"(x));
    return r;
}
__device__ __forceinline__ void ffma2(u64& d, u64 a, u64 b) {
    asm("fma.rn.f32x2 %0, %1, %2, %0;" : "+l"(d) : "l"(a), "l"(b));
}

// Load 6x10x48 input patch (zero-padded) into smem, optionally applying BN.
// BN applies ONLY to in-bounds pixels -- padding of the normalized tensor is exact zero.
template <bool BN>
__device__ __forceinline__ void load_patch(const float* __restrict__ src,  // image base [H,W,48]
                                           float* s_in, int gy0, int gx0, int tid,
                                           const float* s_scale, const float* s_shift) {
    for (int p = tid; p < PATCH_FLOATS / 4; p += 128) {  // 60 pixels * 12 float4
        int pix = p / 12, cv = p - pix * 12;
        int py = pix / 10, px = pix - py * 10;
        int gy = gy0 + py, gx = gx0 + px;
        float4 v = make_float4(0.f, 0.f, 0.f, 0.f);
        if ((unsigned)gy < HH && (unsigned)gx < WW) {
            v = *(const float4*)(src + ((size_t)gy * WW + gx) * CIN + cv * 4);
            if (BN) {
                int c = cv * 4;
                v.x = v.x * s_scale[c + 0] + s_shift[c + 0];
                v.y = v.y * s_scale[c + 1] + s_shift[c + 1];
                v.z = v.z * s_scale[c + 2] + s_shift[c + 2];
                v.w = v.w * s_scale[c + 3] + s_shift[c + 3];
            }
        }
        ((float4*)s_in)[p] = v;
    }
}

// Conv core: accumulate 3x3x48 -> 192 for this thread's 4 spatial x 6 packed-oc-pair tile.
// Thread og (0..15) owns oc pairs {32*j + 2*og : j=0..5} -> weight LDS.64 conflict-free.
__device__ __forceinline__ void conv_accum(const float* __restrict__ Wg,  // [3,3,48,192]
                                           const float* s_in, float* s_w,
                                           u64 acc[4][6],
                                           int tid, int sy, int sx0, int og) {
#pragma unroll 1
    for (int kk = 0; kk < 9; kk++) {
        __syncthreads();
        // stage 48x192 weight slice for this (kh,kw): 2304 float4 by 128 threads
        const float4* wsrc = (const float4*)(Wg + (size_t)kk * CIN * OCC);
        float4* wdst = (float4*)s_w;
#pragma unroll
        for (int p = 0; p < 18; p++) wdst[tid + p * 128] = wsrc[tid + p * 128];
        __syncthreads();

        int kh = kk / 3, kw = kk - kh * 3;
        const float* inrow = s_in + ((sy + kh) * 10 + sx0 + kw) * CIN;
        const float* wcol = s_w + 2 * og;
#pragma unroll 2
        for (int c = 0; c < CIN; c++) {
            u64 a0 = bcast2(inrow[c]);
            u64 a1 = bcast2(inrow[c + CIN]);
            u64 a2 = bcast2(inrow[c + 2 * CIN]);
            u64 a3 = bcast2(inrow[c + 3 * CIN]);
            const u64* w2 = (const u64*)(wcol + c * OCC);
            u64 wv[6];
#pragma unroll
            for (int j = 0; j < 6; j++) wv[j] = w2[16 * j];  // stride 32 floats
#pragma unroll
            for (int j = 0; j < 6; j++) {
                ffma2(acc[0][j], a0, wv[j]);
                ffma2(acc[1][j], a1, wv[j]);
                ffma2(acc[2][j], a2, wv[j]);
                ffma2(acc[3][j], a3, wv[j]);
            }
        }
    }
}

// conv(input, Wx) + b over all 64 (b,t) images. BN=true reads g_h1 and applies BN first.
template <bool BN>
__global__ void __launch_bounds__(128, 4) convx_kernel(
    const float* __restrict__ xin, const float* __restrict__ Wx,
    const float* __restrict__ bias,
    const float* __restrict__ gamma, const float* __restrict__ beta,
    const float* __restrict__ mean, const float* __restrict__ var) {
    extern __shared__ float sm[];
    float* s_in = sm;                 // 2880 floats
    float* s_w  = sm + PATCH_FLOATS;  // 9216 floats
    __shared__ float s_scale[CIN], s_shift[CIN];

    int tid = threadIdx.x;
    int img = blockIdx.z;  // b*T + t
    int gy0 = blockIdx.y * 4 - 1, gx0 = blockIdx.x * 8 - 1;

    if (BN) {
        if (tid < CIN) {
            float sc = gamma[tid] * rsqrtf(var[tid] + 1e-3f);
            s_scale[tid] = sc;
            s_shift[tid] = beta[tid] - mean[tid] * sc;
        }
        __syncthreads();
    }
    const float* src = BN ? (g_h1 + (size_t)img * HH * WW * NF)
                          : (xin + (size_t)img * HH * WW * CIN);
    load_patch<BN>(src, s_in, gy0, gx0, tid, s_scale, s_shift);

    int og = tid & 15, sg = tid >> 4;      // sg 0..7: 8 spatial quads
    int sy = sg >> 1, sx0 = (sg & 1) * 4;  // sy 0..3, sx0 in {0,4}

    u64 acc[4][6];
    {
        const float* bp = bias + 2 * og;
#pragma unroll
        for (int j = 0; j < 6; j++) {
            u64 bv = *(const u64*)(bp + 32 * j);
            acc[0][j] = bv; acc[1][j] = bv; acc[2][j] = bv; acc[3][j] = bv;
        }
    }
    conv_accum(Wx, s_in, s_w, acc, tid, sy, sx0, og);

#pragma unroll
    for (int i = 0; i < 4; i++) {
        int y = blockIdx.y * 4 + sy, x = blockIdx.x * 8 + sx0 + i;
        float* dst = g_zx + (((size_t)img * HH + y) * WW + x) * OCC + 2 * og;
#pragma unroll
        for (int j = 0; j < 6; j++)
            *(u64*)(dst + 32 * j) = acc[i][j];
    }
}

// One recurrent step: z = zx[t] + conv(h,Wh); gates; update c,h.
// LAYER 1 -> write h to g_h1 sequence; LAYER 2 -> write out = x + h.
template <int LAYER>
__global__ void __launch_bounds__(128, 4) step_kernel(
    const float* __restrict__ Wh, int t, int parity,
    const float* __restrict__ xres, float* __restrict__ out) {
    extern __shared__ float sm[];
    float* s_in = sm;
    float* s_w  = sm + PATCH_FLOATS;
    float* s_z  = sm;  // reuses patch+weight region after conv (needs 6144 floats)

    int tid = threadIdx.x;
    int b = blockIdx.z;
    int gy0 = blockIdx.y * 4 - 1, gx0 = blockIdx.x * 8 - 1;

    const float* hin = parity ? g_hB : g_hA;
    float* hout      = parity ? g_hA : g_hB;

    load_patch<false>(hin + (size_t)b * HH * WW * NF, s_in, gy0, gx0, tid, nullptr, nullptr);

    int og = tid & 15, sg = tid >> 4;
    int sy = sg >> 1, sx0 = (sg & 1) * 4;

    u64 acc[4][6];
#pragma unroll
    for (int i = 0; i < 4; i++)
#pragma unroll
        for (int j = 0; j < 6; j++) acc[i][j] = 0ull;

    conv_accum(Wh, s_in, s_w, acc, tid, sy, sx0, og);

    __syncthreads();  // all smem reads done; safe to overwrite with z
#pragma unroll
    for (int i = 0; i < 4; i++) {
        int s = sy * 8 + sx0 + i;  // 0..31 local spatial
        float* dst = s_z + s * OCC + 2 * og;
#pragma unroll
        for (int j = 0; j < 6; j++)
            *(u64*)(dst + 32 * j) = acc[i][j];  // banks 2og,2og+1: conflict-free
    }
    __syncthreads();

    int imgt = b * TT + t;
#pragma unroll 1
    for (int k = 0; k < 12; k++) {
        int e = tid + k * 128;         // 0..1535: 32 spatial x 48 f-channels
        int s = e / 48, f = e - s * 48;
        int yy = gy0 + 1 + (s >> 3);
        int xx = gx0 + 1 + (s & 7);
        size_t zoff = (((size_t)imgt * HH + yy) * WW + xx) * OCC;
        const float* zx = g_zx + zoff;
        float zi = s_z[s * OCC + f]          + zx[f];
        float zf = s_z[s * OCC + f + NF]     + zx[f + NF];
        float zg = s_z[s * OCC + f + 2 * NF] + zx[f + 2 * NF];
        float zo = s_z[s * OCC + f + 3 * NF] + zx[f + 3 * NF];

        size_t hoff = (((size_t)b * HH + yy) * WW + xx) * NF + f;
        float cold = g_c[hoff];
        float cn = hsig(zf) * cold + hsig(zi) * tanhf(zg);
        float hn = hsig(zo) * tanhf(cn);
        g_c[hoff]  = cn;
        hout[hoff] = hn;

        size_t ooff = (((size_t)imgt * HH + yy) * WW + xx) * NF + f;
        if (LAYER == 1)
            g_h1[ooff] = hn;
        else
            out[ooff] = xres[ooff] + hn;
    }
}

extern "C" void kernel_launch(void* const* d_in, const int* in_sizes, int n_in,
                              void* d_out, int out_size) {
    const float* x     = (const float*)d_in[0];
    const float* Wx1   = (const float*)d_in[1];
    const float* Wh1   = (const float*)d_in[2];
    const float* b1    = (const float*)d_in[3];
    const float* Wx2   = (const float*)d_in[4];
    const float* Wh2   = (const float*)d_in[5];
    const float* b2    = (const float*)d_in[6];
    const float* gamma = (const float*)d_in[7];
    const float* beta  = (const float*)d_in[8];
    const float* mean  = (const float*)d_in[9];
    const float* var   = (const float*)d_in[10];
    float* out = (float*)d_out;

    cudaFuncSetAttribute((const void*)convx_kernel<false>,
                         cudaFuncAttributeMaxDynamicSharedMemorySize, SMEM_BYTES);
    cudaFuncSetAttribute((const void*)convx_kernel<true>,
                         cudaFuncAttributeMaxDynamicSharedMemorySize, SMEM_BYTES);
    cudaFuncSetAttribute((const void*)step_kernel<1>,
                         cudaFuncAttributeMaxDynamicSharedMemorySize, SMEM_BYTES);
    cudaFuncSetAttribute((const void*)step_kernel<2>,
                         cudaFuncAttributeMaxDynamicSharedMemorySize, SMEM_BYTES);

    dim3 blk(128);
    dim3 gridx(8, 16, BB * TT);  // 8x4 tiles over all (b,t) images
    dim3 grids(8, 16, BB);       // one recurrent step: 512 blocks

    // ---- Layer 1 ----
    zero_state_kernel<<<256, 256>>>();
    convx_kernel<false><<<gridx, blk, SMEM_BYTES>>>(x, Wx1, b1,
                                                    nullptr, nullptr, nullptr, nullptr);
    for (int t = 0; t < TT; t++)
        step_kernel<1><<<grids, blk, SMEM_BYTES>>>(Wh1, t, t & 1, nullptr, nullptr);

    // ---- Layer 2 (BN folded into Zx conv's input load) ----
    zero_state_kernel<<<256, 256>>>();
    convx_kernel<true><<<gridx, blk, SMEM_BYTES>>>(nullptr, Wx2, b2,
                                                   gamma, beta, mean, var);
    for (int t = 0; t < TT; t++)
        step_kernel<2><<<grids, blk, SMEM_BYTES>>>(Wh2, t, t & 1, x, out);
}